// round 7
// baseline (speedup 1.0000x reference)
#include <cuda_runtime.h>

// Perona-Malik diffusion, 3 iterations fused in ONE kernel.
// Warp-register temporal pipeline (6 stages), 4 cols/lane, horizontal via
// shuffles, vertical via register sliding window.
// R7: packed f32x2 arithmetic (fma/add/mul.rn.f32x2 -> FFMA2/FADD2/FMUL2,
// never emitted by ptxas from C++) for ~18% fewer issued instructions.
// Loads/stores as ulonglong2 so lane data lives natively in 64-bit pairs.

#define NB 16
#define H  1024
#define W  1024

#define HALO   8
#define OUTWC  112
#define NSTRIP 10
#define CHUNK  32
#define WPB    4

#define K2_64  0.16f            // 64 * kappa^2
#define K2E    0.16000064f      // 64 * (kappa^2 + eps)
#define DTC    0.00390625f      // DT / 64  (= 2^-8, exact)

typedef unsigned long long u64;

// packed-pair helpers --------------------------------------------------------
__device__ __forceinline__ u64 pk(float lo, float hi) {
    u64 r; asm("mov.b64 %0, {%1, %2};" : "=l"(r) : "f"(lo), "f"(hi)); return r;
}
__device__ __forceinline__ void unpk(u64 p, float& lo, float& hi) {
    asm("mov.b64 {%0, %1}, %2;" : "=f"(lo), "=f"(hi) : "l"(p));
}
__device__ __forceinline__ u64 add2(u64 a, u64 b) {
    u64 r; asm("add.rn.f32x2 %0, %1, %2;" : "=l"(r) : "l"(a), "l"(b)); return r;
}
__device__ __forceinline__ u64 mul2(u64 a, u64 b) {
    u64 r; asm("mul.rn.f32x2 %0, %1, %2;" : "=l"(r) : "l"(a), "l"(b)); return r;
}
__device__ __forceinline__ u64 fma2(u64 a, u64 b, u64 c) {
    u64 r; asm("fma.rn.f32x2 %0, %1, %2, %3;" : "=l"(r) : "l"(a), "l"(b), "l"(c)); return r;
}
__device__ __forceinline__ u64 bcast2(float v) {
    unsigned u = __float_as_uint(v); return ((u64)u << 32) | u;
}

#define TWO2  0x4000000040000000ULL   // (2.0f, 2.0f)
#define NEG12 0xBF800000BF800000ULL   // (-1.0f, -1.0f)
// sub2(y - x) = fma2(x, NEG12, y)

__device__ __forceinline__ float shup(float v)  { return __shfl_up_sync(0xffffffffu, v, 1); }
__device__ __forceinline__ float shdn(float v)  { return __shfl_down_sync(0xffffffffu, v, 1); }

struct F2   { u64 a, b; };                       // 4 floats: cols 0-1, 2-3
struct Flux { u64 fx01, fx23, fy01, fy23; };

// flux (scaled by 8) at one row from input rows vm, vc, vp.
template<bool GUARD>
__device__ __forceinline__ Flux fluxrow(const F2 vm, const F2 vc, const F2 vp,
                                        const bool valid, const u64 K2E2)
{
    const u64 a01 = fma2(vc.a, TWO2, add2(vm.a, vp.a));   // 8*smooth_y
    const u64 a23 = fma2(vc.b, TWO2, add2(vm.b, vp.b));
    const u64 b01 = fma2(vm.a, NEG12, vp.a);              // diff_y
    const u64 b23 = fma2(vm.b, NEG12, vp.b);

    float a0, a1, a2, a3, b0, b1, b2, b3;
    unpk(a01, a0, a1); unpk(a23, a2, a3);
    unpk(b01, b0, b1); unpk(b23, b2, b3);

    const float aL = shup(a3), aR = shdn(a0);
    const float bL = shup(b3), bR = shdn(b0);

    const u64 A12 = pk(a1, a2);
    const u64 gx01 = fma2(pk(aL, a0), NEG12, A12);        // (a1-aL, a2-a0) = 8*gx
    const u64 gx23 = fma2(A12, NEG12, pk(a3, aR));        // (a3-a1, aR-a2)
    const u64 B12 = pk(b1, b2);
    const u64 gy01 = fma2(b01, TWO2, add2(pk(bL, b0), B12));   // 8*gy
    const u64 gy23 = fma2(b23, TWO2, add2(B12, pk(b3, bR)));

    const u64 d01 = fma2(gx01, gx01, fma2(gy01, gy01, K2E2));
    const u64 d23 = fma2(gx23, gx23, fma2(gy23, gy23, K2E2));

    float d0, d1, d2, d3;
    unpk(d01, d0, d1); unpk(d23, d2, d3);
    float c0 = __fdividef(K2_64, d0);
    float c1 = __fdividef(K2_64, d1);
    float c2 = __fdividef(K2_64, d2);
    float c3 = __fdividef(K2_64, d3);
    if (GUARD) {
        c0 = valid ? c0 : 0.f;  c1 = valid ? c1 : 0.f;
        c2 = valid ? c2 : 0.f;  c3 = valid ? c3 : 0.f;
    }
    const u64 c01 = pk(c0, c1), c23 = pk(c2, c3);

    Flux f;
    f.fx01 = mul2(c01, gx01);  f.fx23 = mul2(c23, gx23);  // 8*flux
    f.fy01 = mul2(c01, gy01);  f.fy23 = mul2(c23, gy23);
    return f;
}

// out = base + (DT/64)*dsum64, from scaled flux rows f0, f1, f2.
template<bool GUARD>
__device__ __forceinline__ F2 updrow(const F2 base, const Flux& f0,
                                     const Flux& f1, const Flux& f2,
                                     const bool valid, const u64 DTC2)
{
    const u64 p01 = fma2(f1.fx01, TWO2, add2(f0.fx01, f2.fx01));
    const u64 p23 = fma2(f1.fx23, TWO2, add2(f0.fx23, f2.fx23));
    const u64 q01 = fma2(f0.fy01, NEG12, f2.fy01);
    const u64 q23 = fma2(f0.fy23, NEG12, f2.fy23);

    float p0, p1, p2, p3, q0, q1, q2, q3;
    unpk(p01, p0, p1); unpk(p23, p2, p3);
    unpk(q01, q0, q1); unpk(q23, q2, q3);

    const float pL = shup(p3), pR = shdn(p0);
    const float qL = shup(q3), qR = shdn(q0);

    const u64 P12 = pk(p1, p2);
    const u64 dx01 = fma2(pk(pL, p0), NEG12, P12);
    const u64 dx23 = fma2(P12, NEG12, pk(p3, pR));
    const u64 Q12 = pk(q1, q2);
    const u64 dy01 = fma2(q01, TWO2, add2(pk(qL, q0), Q12));
    const u64 dy23 = fma2(q23, TWO2, add2(Q12, pk(q3, qR)));

    F2 o;
    o.a = fma2(add2(dx01, dy01), DTC2, base.a);
    o.b = fma2(add2(dx23, dy23), DTC2, base.b);
    if (GUARD) {
        o.a = valid ? o.a : 0ull;
        o.b = valid ? o.b : 0ull;
    }
    return o;
}

// GUARD=true: boundary warps; GUARD=false: fully interior (no checks).
template<bool GUARD>
__device__ __forceinline__ void run_strip(const float* __restrict__ img,
                                          float* __restrict__ op,
                                          const int x0, const int y0,
                                          const bool colv, const bool st_ok)
{
    const u64 K2E2 = bcast2(K2E);
    const u64 DTC2 = bcast2(DTC);

    auto load = [&](int y) -> F2 {
        F2 r;
        if (GUARD) {
            if (colv && (unsigned)y < (unsigned)H) {
                const ulonglong2 v = __ldg(reinterpret_cast<const ulonglong2*>(
                                               img + (size_t)y * W + x0));
                r.a = v.x; r.b = v.y;
            } else {
                r.a = 0ull; r.b = 0ull;
            }
        } else {
            const ulonglong2 v = __ldg(reinterpret_cast<const ulonglong2*>(
                                           img + (size_t)y * W + x0));
            r.a = v.x; r.b = v.y;
        }
        return r;
    };
    auto rv = [&](int y) -> bool {
        return GUARD ? (colv && (unsigned)y < (unsigned)H) : true;
    };

    F2 i0 = load(y0 - 6);
    F2 i1 = load(y0 - 5);
    F2 i2 = load(y0 - 4);

    Flux zf; zf.fx01 = zf.fx23 = zf.fy01 = zf.fy23 = 0ull;
    Flux f1a = zf, f1b = zf, f2a = zf, f2b = zf, f3a = zf, f3b = zf;
    F2 zo; zo.a = zo.b = 0ull;
    F2 o1a = zo, o1b = zo, o2a = zo, o2b = zo;

    #pragma unroll 2
    for (int y = y0 - 10; y < y0 + CHUNK; ++y) {
        const F2 inext = load(y + 7);

        const Flux f1c = fluxrow<GUARD>(i0, i1, i2,         rv(y + 5), K2E2);
        const F2   o1c = updrow <GUARD>(i0, f1a, f1b, f1c,  rv(y + 4), DTC2);
        const Flux f2c = fluxrow<GUARD>(o1a, o1b, o1c,      rv(y + 3), K2E2);
        const F2   o2c = updrow <GUARD>(o1a, f2a, f2b, f2c, rv(y + 2), DTC2);
        const Flux f3c = fluxrow<GUARD>(o2a, o2b, o2c,      rv(y + 1), K2E2);
        const F2   o3  = updrow <GUARD>(o2a, f3a, f3b, f3c, rv(y),     DTC2);

        if (st_ok && y >= y0) {
            ulonglong2 v; v.x = o3.a; v.y = o3.b;
            *reinterpret_cast<ulonglong2*>(op + (size_t)y * W + x0) = v;
        }

        i0 = i1; i1 = i2; i2 = inext;
        f1a = f1b; f1b = f1c;
        o1a = o1b; o1b = o1c;
        f2a = f2b; f2b = f2c;
        o2a = o2b; o2b = o2c;
        f3a = f3b; f3b = f3c;
    }
}

__global__ __launch_bounds__(128, 4)
void pm_fused3(const float* __restrict__ in, float* __restrict__ out)
{
    const int lane = threadIdx.x & 31;
    const int warp = threadIdx.x >> 5;
    const int bx   = blockIdx.x;

    const int x0 = bx * OUTWC - HALO + lane * 4;
    const int y0 = (blockIdx.y * WPB + warp) * CHUNK;

    const size_t plane = (size_t)blockIdx.z * (size_t)(H * W);
    const float* __restrict__ img = in  + plane;
    float*       __restrict__ op  = out + plane;

    const bool colv  = (x0 >= 0) && (x0 + 4 <= W);
    const bool st_ok = colv && (lane >= HALO / 4) && (lane < 32 - HALO / 4);

    const bool interior = (bx >= 1) && (bx <= NSTRIP - 2) &&
                          (y0 >= 6) && (y0 + CHUNK + 6 < H);

    if (interior)
        run_strip<false>(img, op, x0, y0, true, st_ok);
    else
        run_strip<true>(img, op, x0, y0, colv, st_ok);
}

extern "C" void kernel_launch(void* const* d_in, const int* in_sizes, int n_in,
                              void* d_out, int out_size)
{
    const float* image = (const float*)d_in[0];
    float* out = (float*)d_out;

    dim3 block(32 * WPB, 1, 1);                  // 128 threads
    dim3 grid(NSTRIP, H / (CHUNK * WPB), NB);    // 10 x 8 x 16 = 1280 blocks

    pm_fused3<<<grid, block>>>(image, out);
}

// round 8
// speedup vs baseline: 1.2487x; 1.2487x over previous
#include <cuda_runtime.h>

// Perona-Malik diffusion, 3 iterations fused in ONE kernel.
// Warp-register temporal pipeline (6 stages), 4 cols/lane via float4,
// horizontal via shuffles, vertical via register sliding window. (R6 base —
// R7's f32x2 packing regressed on ALU mov overhead and is reverted.)
// R8: CHUNK=64 at unchanged occupancy (256-thread blocks, 128-reg cap,
// 16 warps/SM) -> 12% fewer pipeline steps; walking pointers; loop split.
// Grid stays 640 blocks (2.16 waves of 2-block residency).

#define NB 16
#define H  1024
#define W  1024

#define HALO   8
#define OUTWC  112
#define NSTRIP 10
#define CHUNK  64

#define K2_64  0.16f            // 64 * kappa^2
#define K2E    0.16000064f      // 64 * (kappa^2 + eps)
#define DTC    0.00390625f      // DT / 64

__device__ __forceinline__ float4 mk4(float v) { return make_float4(v, v, v, v); }

struct Flux { float4 fx, fy; };

__device__ __forceinline__ Flux fluxrow(const float4 vm, const float4 vc,
                                        const float4 vp, const bool valid)
{
    const unsigned m = 0xffffffffu;
    const float a0 = vm.x + 2.f*vc.x + vp.x;
    const float a1 = vm.y + 2.f*vc.y + vp.y;
    const float a2 = vm.z + 2.f*vc.z + vp.z;
    const float a3 = vm.w + 2.f*vc.w + vp.w;
    const float b0 = vp.x - vm.x;
    const float b1 = vp.y - vm.y;
    const float b2 = vp.z - vm.z;
    const float b3 = vp.w - vm.w;
    const float aL = __shfl_up_sync(m, a3, 1);
    const float aR = __shfl_down_sync(m, a0, 1);
    const float bL = __shfl_up_sync(m, b3, 1);
    const float bR = __shfl_down_sync(m, b0, 1);
    const float gx0 = a1 - aL;
    const float gx1 = a2 - a0;
    const float gx2 = a3 - a1;
    const float gx3 = aR - a2;
    const float gy0 = bL + 2.f*b0 + b1;
    const float gy1 = b0 + 2.f*b1 + b2;
    const float gy2 = b1 + 2.f*b2 + b3;
    const float gy3 = b2 + 2.f*b3 + bR;
    const float d0 = fmaf(gx0, gx0, fmaf(gy0, gy0, K2E));
    const float d1 = fmaf(gx1, gx1, fmaf(gy1, gy1, K2E));
    const float d2 = fmaf(gx2, gx2, fmaf(gy2, gy2, K2E));
    const float d3 = fmaf(gx3, gx3, fmaf(gy3, gy3, K2E));
    const float c0 = valid ? __fdividef(K2_64, d0) : 0.f;
    const float c1 = valid ? __fdividef(K2_64, d1) : 0.f;
    const float c2 = valid ? __fdividef(K2_64, d2) : 0.f;
    const float c3 = valid ? __fdividef(K2_64, d3) : 0.f;
    Flux f;
    f.fx = make_float4(c0*gx0, c1*gx1, c2*gx2, c3*gx3);
    f.fy = make_float4(c0*gy0, c1*gy1, c2*gy2, c3*gy3);
    return f;
}

__device__ __forceinline__ float4 updrow(const float4 base,
                                         const Flux f0, const Flux f1,
                                         const Flux f2, const bool valid)
{
    const unsigned m = 0xffffffffu;
    const float p0 = f0.fx.x + 2.f*f1.fx.x + f2.fx.x;
    const float p1 = f0.fx.y + 2.f*f1.fx.y + f2.fx.y;
    const float p2 = f0.fx.z + 2.f*f1.fx.z + f2.fx.z;
    const float p3 = f0.fx.w + 2.f*f1.fx.w + f2.fx.w;
    const float q0 = f2.fy.x - f0.fy.x;
    const float q1 = f2.fy.y - f0.fy.y;
    const float q2 = f2.fy.z - f0.fy.z;
    const float q3 = f2.fy.w - f0.fy.w;
    const float pL = __shfl_up_sync(m, p3, 1);
    const float pR = __shfl_down_sync(m, p0, 1);
    const float qL = __shfl_up_sync(m, q3, 1);
    const float qR = __shfl_down_sync(m, q0, 1);
    const float d0 = (p1 - pL) + (qL + 2.f*q0 + q1);
    const float d1 = (p2 - p0) + (q0 + 2.f*q1 + q2);
    const float d2 = (p3 - p1) + (q1 + 2.f*q2 + q3);
    const float d3 = (pR - p2) + (q2 + 2.f*q3 + qR);
    float4 o;
    o.x = valid ? fmaf(DTC, d0, base.x) : 0.f;
    o.y = valid ? fmaf(DTC, d1, base.y) : 0.f;
    o.z = valid ? fmaf(DTC, d2, base.z) : 0.f;
    o.w = valid ? fmaf(DTC, d3, base.w) : 0.f;
    return o;
}

template<bool GUARD>
__device__ __forceinline__ void run_strip(const float* __restrict__ img,
                                          float* __restrict__ op,
                                          const int x0, const int y0,
                                          const bool colv, const bool st_ok)
{
    const float* lp = img + (size_t)(y0 - 6) * W + x0;
    float*       sp = op  + (size_t)y0 * W + x0;

    int ly = y0 - 6;
    auto load = [&]() -> float4 {
        float4 v;
        if (GUARD) {
            v = (colv && (unsigned)ly < (unsigned)H)
                    ? __ldg(reinterpret_cast<const float4*>(lp)) : mk4(0.f);
            ++ly;
        } else {
            v = __ldg(reinterpret_cast<const float4*>(lp));
        }
        lp += W;
        return v;
    };
    auto rv = [&](int y) -> bool {
        return GUARD ? (colv && (unsigned)y < (unsigned)H) : true;
    };

    float4 i0 = load();
    float4 i1 = load();
    float4 i2 = load();

    Flux zf; zf.fx = mk4(0.f); zf.fy = mk4(0.f);
    Flux  f1a = zf, f1b = zf, f2a = zf, f2b = zf, f3a = zf, f3b = zf;
    float4 o1a = mk4(0.f), o1b = o1a, o2a = o1a, o2b = o1a;

    auto step = [&](int y) -> float4 {
        const float4 inext = load();
        const Flux   f1c = fluxrow(i0, i1, i2,         rv(y + 5));
        const float4 o1c = updrow (i0, f1a, f1b, f1c,  rv(y + 4));
        const Flux   f2c = fluxrow(o1a, o1b, o1c,      rv(y + 3));
        const float4 o2c = updrow (o1a, f2a, f2b, f2c, rv(y + 2));
        const Flux   f3c = fluxrow(o2a, o2b, o2c,      rv(y + 1));
        const float4 o3  = updrow (o2a, f3a, f3b, f3c, rv(y));
        i0 = i1; i1 = i2; i2 = inext;
        f1a = f1b; f1b = f1c;
        o1a = o1b; o1b = o1c;
        f2a = f2b; f2b = f2c;
        o2a = o2b; o2b = o2c;
        f3a = f3b; f3b = f3c;
        return o3;
    };

    #pragma unroll 2
    for (int y = y0 - 10; y < y0; ++y)
        (void)step(y);

    #pragma unroll 2
    for (int y = y0; y < y0 + CHUNK; ++y) {
        const float4 o3 = step(y);
        if (st_ok)
            *reinterpret_cast<float4*>(sp) = o3;
        sp += W;
    }
}

__global__ __launch_bounds__(256, 2)        // cap 128 regs, 16 warps/SM
void pm_fused3(const float* __restrict__ in, float* __restrict__ out)
{
    const int lane = threadIdx.x & 31;
    const int warp = threadIdx.x >> 5;      // 0..7
    const int bx   = blockIdx.x;

    const int x0 = bx * OUTWC - HALO + lane * 4;
    // each block covers 8 consecutive CHUNK-row bands -> 512 rows; grid.y=2
    const int y0 = (blockIdx.y * 8 + warp) * CHUNK;

    const size_t plane = (size_t)blockIdx.z * (size_t)(H * W);
    const float* __restrict__ img = in  + plane;
    float*       __restrict__ op  = out + plane;

    const bool colv  = (x0 >= 0) && (x0 + 4 <= W);
    const bool st_ok = colv && (lane >= HALO / 4) && (lane < 32 - HALO / 4);

    const bool interior = (bx >= 1) && (bx <= NSTRIP - 2) &&
                          (y0 >= 6) && (y0 + CHUNK + 6 < H);

    if (interior)
        run_strip<false>(img, op, x0, y0, true, st_ok);
    else
        run_strip<true>(img, op, x0, y0, colv, st_ok);
}

extern "C" void kernel_launch(void* const* d_in, const int* in_sizes, int n_in,
                              void* d_out, int out_size)
{
    const float* image = (const float*)d_in[0];
    float* out = (float*)d_out;

    dim3 block(256, 1, 1);
    dim3 grid(NSTRIP, H / (CHUNK * 8), NB);   // 10 x 2 x 16 = 320 blocks

    pm_fused3<<<grid, block>>>(image, out);
}

// round 9
// speedup vs baseline: 1.6159x; 1.2940x over previous
#include <cuda_runtime.h>

// Perona-Malik diffusion, 3 iterations fused in ONE kernel.
// Warp-register temporal pipeline (6 stages), 4 cols/lane via float4,
// horizontal via shuffles, vertical via register sliding window.
// R9: exactly-one-wave scheduling. 2240 warp-strips (10 strips x 14 bands
// x 16 images, CHUNK=74) packed into 560 blocks x 4 warps <= 592 resident
// block slots at the 128-reg cap -> single wave, no tail, warm-up overhead
// 12% (was 24% at CHUNK=32).

#define NB 16
#define H  1024
#define W  1024

#define HALO   8
#define OUTWC  112
#define NSTRIP 10
#define CHUNK  74
#define NBANDS 14     // 14*74 = 1036 >= 1024 (last band stores 62 rows)

#define K2_64  0.16f            // 64 * kappa^2
#define K2E    0.16000064f      // 64 * (kappa^2 + eps)
#define DTC    0.00390625f      // DT / 64

__device__ __forceinline__ float4 mk4(float v) { return make_float4(v, v, v, v); }

struct Flux { float4 fx, fy; };

// flux (scaled by 8) at one row from input rows vm, vc, vp.
__device__ __forceinline__ Flux fluxrow(const float4 vm, const float4 vc,
                                        const float4 vp, const bool valid)
{
    const unsigned m = 0xffffffffu;
    const float a0 = vm.x + 2.f*vc.x + vp.x;
    const float a1 = vm.y + 2.f*vc.y + vp.y;
    const float a2 = vm.z + 2.f*vc.z + vp.z;
    const float a3 = vm.w + 2.f*vc.w + vp.w;
    const float b0 = vp.x - vm.x;
    const float b1 = vp.y - vm.y;
    const float b2 = vp.z - vm.z;
    const float b3 = vp.w - vm.w;
    const float aL = __shfl_up_sync(m, a3, 1);
    const float aR = __shfl_down_sync(m, a0, 1);
    const float bL = __shfl_up_sync(m, b3, 1);
    const float bR = __shfl_down_sync(m, b0, 1);
    const float gx0 = a1 - aL;                 // 8*gx
    const float gx1 = a2 - a0;
    const float gx2 = a3 - a1;
    const float gx3 = aR - a2;
    const float gy0 = bL + 2.f*b0 + b1;        // 8*gy
    const float gy1 = b0 + 2.f*b1 + b2;
    const float gy2 = b1 + 2.f*b2 + b3;
    const float gy3 = b2 + 2.f*b3 + bR;
    const float d0 = fmaf(gx0, gx0, fmaf(gy0, gy0, K2E));
    const float d1 = fmaf(gx1, gx1, fmaf(gy1, gy1, K2E));
    const float d2 = fmaf(gx2, gx2, fmaf(gy2, gy2, K2E));
    const float d3 = fmaf(gx3, gx3, fmaf(gy3, gy3, K2E));
    const float c0 = valid ? __fdividef(K2_64, d0) : 0.f;
    const float c1 = valid ? __fdividef(K2_64, d1) : 0.f;
    const float c2 = valid ? __fdividef(K2_64, d2) : 0.f;
    const float c3 = valid ? __fdividef(K2_64, d3) : 0.f;
    Flux f;
    f.fx = make_float4(c0*gx0, c1*gx1, c2*gx2, c3*gx3);   // 8*flux
    f.fy = make_float4(c0*gy0, c1*gy1, c2*gy2, c3*gy3);
    return f;
}

// out = base + (DT/64) * dsum8, from scaled flux rows f0,f1,f2.
__device__ __forceinline__ float4 updrow(const float4 base,
                                         const Flux f0, const Flux f1,
                                         const Flux f2, const bool valid)
{
    const unsigned m = 0xffffffffu;
    const float p0 = f0.fx.x + 2.f*f1.fx.x + f2.fx.x;
    const float p1 = f0.fx.y + 2.f*f1.fx.y + f2.fx.y;
    const float p2 = f0.fx.z + 2.f*f1.fx.z + f2.fx.z;
    const float p3 = f0.fx.w + 2.f*f1.fx.w + f2.fx.w;
    const float q0 = f2.fy.x - f0.fy.x;
    const float q1 = f2.fy.y - f0.fy.y;
    const float q2 = f2.fy.z - f0.fy.z;
    const float q3 = f2.fy.w - f0.fy.w;
    const float pL = __shfl_up_sync(m, p3, 1);
    const float pR = __shfl_down_sync(m, p0, 1);
    const float qL = __shfl_up_sync(m, q3, 1);
    const float qR = __shfl_down_sync(m, q0, 1);
    const float d0 = (p1 - pL) + (qL + 2.f*q0 + q1);
    const float d1 = (p2 - p0) + (q0 + 2.f*q1 + q2);
    const float d2 = (p3 - p1) + (q1 + 2.f*q2 + q3);
    const float d3 = (pR - p2) + (q2 + 2.f*q3 + qR);
    float4 o;
    o.x = valid ? fmaf(DTC, d0, base.x) : 0.f;
    o.y = valid ? fmaf(DTC, d1, base.y) : 0.f;
    o.z = valid ? fmaf(DTC, d2, base.z) : 0.f;
    o.w = valid ? fmaf(DTC, d3, base.w) : 0.f;
    return o;
}

// GUARD=true: boundary warps (x or y edge), full predication, variable rows.
// GUARD=false: fully interior warps, no checks, compile-time row count.
template<bool GUARD>
__device__ __forceinline__ void run_strip(const float* __restrict__ img,
                                          float* __restrict__ op,
                                          const int x0, const int y0,
                                          const int nrows,
                                          const bool colv, const bool st_ok)
{
    const float* lp = img + (size_t)(y0 - 6) * W + x0;   // next row to load
    float*       sp = op  + (size_t)y0 * W + x0;         // next row to store

    int ly = y0 - 6;
    auto load = [&]() -> float4 {
        float4 v;
        if (GUARD) {
            v = (colv && (unsigned)ly < (unsigned)H)
                    ? __ldg(reinterpret_cast<const float4*>(lp)) : mk4(0.f);
            ++ly;
        } else {
            v = __ldg(reinterpret_cast<const float4*>(lp));
        }
        lp += W;
        return v;
    };
    auto rv = [&](int y) -> bool {
        return GUARD ? (colv && (unsigned)y < (unsigned)H) : true;
    };

    float4 i0 = load();
    float4 i1 = load();
    float4 i2 = load();

    Flux zf; zf.fx = mk4(0.f); zf.fy = mk4(0.f);
    Flux  f1a = zf, f1b = zf, f2a = zf, f2b = zf, f3a = zf, f3b = zf;
    float4 o1a = mk4(0.f), o1b = o1a, o2a = o1a, o2b = o1a;

    auto step = [&](int y) -> float4 {
        const float4 inext = load();
        const Flux   f1c = fluxrow(i0, i1, i2,         rv(y + 5));
        const float4 o1c = updrow (i0, f1a, f1b, f1c,  rv(y + 4));
        const Flux   f2c = fluxrow(o1a, o1b, o1c,      rv(y + 3));
        const float4 o2c = updrow (o1a, f2a, f2b, f2c, rv(y + 2));
        const Flux   f3c = fluxrow(o2a, o2b, o2c,      rv(y + 1));
        const float4 o3  = updrow (o2a, f3a, f3b, f3c, rv(y));
        i0 = i1; i1 = i2; i2 = inext;
        f1a = f1b; f1b = f1c;
        o1a = o1b; o1b = o1c;
        f2a = f2b; f2b = f2c;
        o2a = o2b; o2b = o2c;
        f3a = f3b; f3b = f3c;
        return o3;
    };

    // warm-up: 10 steps, nothing stored
    #pragma unroll 2
    for (int y = y0 - 10; y < y0; ++y)
        (void)step(y);

    if (GUARD) {
        for (int y = y0; y < y0 + nrows; ++y) {
            const float4 o3 = step(y);
            if (st_ok)
                *reinterpret_cast<float4*>(sp) = o3;
            sp += W;
        }
    } else {
        #pragma unroll 2
        for (int y = y0; y < y0 + CHUNK; ++y) {
            const float4 o3 = step(y);
            if (st_ok)
                *reinterpret_cast<float4*>(sp) = o3;
            sp += W;
        }
    }
}

__global__ __launch_bounds__(128, 4)       // cap 128 regs -> 4 blocks/SM
void pm_fused3(const float* __restrict__ in, float* __restrict__ out)
{
    const int lane = threadIdx.x & 31;
    const int warp = threadIdx.x >> 5;

    // flattened work item: 10 strips x 14 bands x 16 images = 2240 warps
    const int item  = blockIdx.x * 4 + warp;
    const int image = item / (NSTRIP * NBANDS);
    const int rem   = item - image * (NSTRIP * NBANDS);
    const int strip = rem / NBANDS;
    const int band  = rem - strip * NBANDS;

    const int x0 = strip * OUTWC - HALO + lane * 4;
    const int y0 = band * CHUNK;
    const int nrows = (band == NBANDS - 1) ? (H - y0) : CHUNK;   // 62 or 74

    const size_t plane = (size_t)image * (size_t)(H * W);
    const float* __restrict__ img = in  + plane;
    float*       __restrict__ op  = out + plane;

    const bool colv  = (x0 >= 0) && (x0 + 4 <= W);
    const bool st_ok = colv && (lane >= HALO / 4) && (lane < 32 - HALO / 4);

    // fully interior warp: all loads in rows [y0-6, y0+CHUNK+6] and all
    // lanes' columns inside the image.
    const bool interior = (strip >= 1) && (strip <= NSTRIP - 2) &&
                          (band >= 1) && (y0 + CHUNK + 6 < H);

    if (interior)
        run_strip<false>(img, op, x0, y0, CHUNK, true, st_ok);
    else
        run_strip<true>(img, op, x0, y0, nrows, colv, st_ok);
}

extern "C" void kernel_launch(void* const* d_in, const int* in_sizes, int n_in,
                              void* d_out, int out_size)
{
    const float* image = (const float*)d_in[0];
    float* out = (float*)d_out;

    // 2240 work items / 4 warps per block = 560 blocks: exactly one wave
    // at 4 blocks/SM residency (592 slots on 148 SMs).
    pm_fused3<<<560, 128>>>(image, out);
}

// round 10
// speedup vs baseline: 1.6672x; 1.0318x over previous
#include <cuda_runtime.h>

// Perona-Malik diffusion, 3 iterations fused in ONE kernel.
// Warp-register temporal pipeline (6 stages), 4 cols/lane via float4,
// horizontal via shuffles, vertical via register sliding window.
// R9 base (exactly-one-wave: 2240 warp-strips in 560 blocks, CHUNK=74).
// R10: (a) grouped reciprocal - one MUFU.RCP per flux row instead of four
// (c_i = prod_{j!=i} d_j * K2/prod(d)), cutting MUFU pipe load 4x;
// (b) u/v divergence identity - updrow needs 2 shuffles instead of 4.

#define NB 16
#define H  1024
#define W  1024

#define HALO   8
#define OUTWC  112
#define NSTRIP 10
#define CHUNK  74
#define NBANDS 14     // 14*74 = 1036 >= 1024 (last band stores 62 rows)

#define K2_64  0.16f            // 64 * kappa^2
#define K2E    0.16000064f      // 64 * (kappa^2 + eps)
#define DTC    0.00390625f      // DT / 64

__device__ __forceinline__ float4 mk4(float v) { return make_float4(v, v, v, v); }

struct Flux { float4 fx, fy; };

// flux (scaled by 8) at one row from input rows vm, vc, vp.
__device__ __forceinline__ Flux fluxrow(const float4 vm, const float4 vc,
                                        const float4 vp, const bool valid)
{
    const unsigned m = 0xffffffffu;
    const float a0 = vm.x + 2.f*vc.x + vp.x;
    const float a1 = vm.y + 2.f*vc.y + vp.y;
    const float a2 = vm.z + 2.f*vc.z + vp.z;
    const float a3 = vm.w + 2.f*vc.w + vp.w;
    const float b0 = vp.x - vm.x;
    const float b1 = vp.y - vm.y;
    const float b2 = vp.z - vm.z;
    const float b3 = vp.w - vm.w;
    const float aL = __shfl_up_sync(m, a3, 1);
    const float aR = __shfl_down_sync(m, a0, 1);
    const float bL = __shfl_up_sync(m, b3, 1);
    const float bR = __shfl_down_sync(m, b0, 1);
    const float gx0 = a1 - aL;                 // 8*gx
    const float gx1 = a2 - a0;
    const float gx2 = a3 - a1;
    const float gx3 = aR - a2;
    const float gy0 = bL + 2.f*b0 + b1;        // 8*gy
    const float gy1 = b0 + 2.f*b1 + b2;
    const float gy2 = b1 + 2.f*b2 + b3;
    const float gy3 = b2 + 2.f*b3 + bR;
    const float d0 = fmaf(gx0, gx0, fmaf(gy0, gy0, K2E));
    const float d1 = fmaf(gx1, gx1, fmaf(gy1, gy1, K2E));
    const float d2 = fmaf(gx2, gx2, fmaf(gy2, gy2, K2E));
    const float d3 = fmaf(gx3, gx3, fmaf(gy3, gy3, K2E));

    // grouped reciprocal: one RCP for four conduction coefficients.
    // c_i = K2/d_i = (prod_{j!=i} d_j) * K2/prod(d)
    const float d01  = d0 * d1;
    const float d23  = d2 * d3;
    const float invK = __fdividef(K2_64, d01 * d23);
    float c0 = (d1 * d23) * invK;
    float c1 = (d0 * d23) * invK;
    float c2 = (d01 * d3) * invK;
    float c3 = (d01 * d2) * invK;
    c0 = valid ? c0 : 0.f;
    c1 = valid ? c1 : 0.f;
    c2 = valid ? c2 : 0.f;
    c3 = valid ? c3 : 0.f;

    Flux f;
    f.fx = make_float4(c0*gx0, c1*gx1, c2*gx2, c3*gx3);   // 8*flux
    f.fy = make_float4(c0*gy0, c1*gy1, c2*gy2, c3*gy3);
    return f;
}

// out = base + (DT/64) * dsum8, from scaled flux rows f0,f1,f2.
// u/v identity: div_i = u_{i+1} + 2*q_i + v_{i-1}, u=p+q, v=q-p
// -> only 2 shuffles (vL, uR) instead of 4.
__device__ __forceinline__ float4 updrow(const float4 base,
                                         const Flux f0, const Flux f1,
                                         const Flux f2, const bool valid)
{
    const unsigned m = 0xffffffffu;
    const float p0 = f0.fx.x + 2.f*f1.fx.x + f2.fx.x;
    const float p1 = f0.fx.y + 2.f*f1.fx.y + f2.fx.y;
    const float p2 = f0.fx.z + 2.f*f1.fx.z + f2.fx.z;
    const float p3 = f0.fx.w + 2.f*f1.fx.w + f2.fx.w;
    const float q0 = f2.fy.x - f0.fy.x;
    const float q1 = f2.fy.y - f0.fy.y;
    const float q2 = f2.fy.z - f0.fy.z;
    const float q3 = f2.fy.w - f0.fy.w;

    const float u0 = p0 + q0, u1 = p1 + q1, u2 = p2 + q2, u3 = p3 + q3;
    const float v0 = q0 - p0, v1 = q1 - p1, v2 = q2 - p2, v3 = q3 - p3;

    const float vL = __shfl_up_sync(m, v3, 1);
    const float uR = __shfl_down_sync(m, u0, 1);

    const float d0 = fmaf(2.f, q0, vL) + u1;
    const float d1 = fmaf(2.f, q1, v0) + u2;
    const float d2 = fmaf(2.f, q2, v1) + u3;
    const float d3 = fmaf(2.f, q3, v2) + uR;

    float4 o;
    o.x = valid ? fmaf(DTC, d0, base.x) : 0.f;
    o.y = valid ? fmaf(DTC, d1, base.y) : 0.f;
    o.z = valid ? fmaf(DTC, d2, base.z) : 0.f;
    o.w = valid ? fmaf(DTC, d3, base.w) : 0.f;
    return o;
}

// GUARD=true: boundary warps (x or y edge), full predication, variable rows.
// GUARD=false: fully interior warps, no checks, compile-time row count.
template<bool GUARD>
__device__ __forceinline__ void run_strip(const float* __restrict__ img,
                                          float* __restrict__ op,
                                          const int x0, const int y0,
                                          const int nrows,
                                          const bool colv, const bool st_ok)
{
    const float* lp = img + (size_t)(y0 - 6) * W + x0;   // next row to load
    float*       sp = op  + (size_t)y0 * W + x0;         // next row to store

    int ly = y0 - 6;
    auto load = [&]() -> float4 {
        float4 v;
        if (GUARD) {
            v = (colv && (unsigned)ly < (unsigned)H)
                    ? __ldg(reinterpret_cast<const float4*>(lp)) : mk4(0.f);
            ++ly;
        } else {
            v = __ldg(reinterpret_cast<const float4*>(lp));
        }
        lp += W;
        return v;
    };
    auto rv = [&](int y) -> bool {
        return GUARD ? (colv && (unsigned)y < (unsigned)H) : true;
    };

    float4 i0 = load();
    float4 i1 = load();
    float4 i2 = load();

    Flux zf; zf.fx = mk4(0.f); zf.fy = mk4(0.f);
    Flux  f1a = zf, f1b = zf, f2a = zf, f2b = zf, f3a = zf, f3b = zf;
    float4 o1a = mk4(0.f), o1b = o1a, o2a = o1a, o2b = o1a;

    auto step = [&](int y) -> float4 {
        const float4 inext = load();
        const Flux   f1c = fluxrow(i0, i1, i2,         rv(y + 5));
        const float4 o1c = updrow (i0, f1a, f1b, f1c,  rv(y + 4));
        const Flux   f2c = fluxrow(o1a, o1b, o1c,      rv(y + 3));
        const float4 o2c = updrow (o1a, f2a, f2b, f2c, rv(y + 2));
        const Flux   f3c = fluxrow(o2a, o2b, o2c,      rv(y + 1));
        const float4 o3  = updrow (o2a, f3a, f3b, f3c, rv(y));
        i0 = i1; i1 = i2; i2 = inext;
        f1a = f1b; f1b = f1c;
        o1a = o1b; o1b = o1c;
        f2a = f2b; f2b = f2c;
        o2a = o2b; o2b = o2c;
        f3a = f3b; f3b = f3c;
        return o3;
    };

    // warm-up: 10 steps, nothing stored
    #pragma unroll 2
    for (int y = y0 - 10; y < y0; ++y)
        (void)step(y);

    if (GUARD) {
        for (int y = y0; y < y0 + nrows; ++y) {
            const float4 o3 = step(y);
            if (st_ok)
                *reinterpret_cast<float4*>(sp) = o3;
            sp += W;
        }
    } else {
        #pragma unroll 2
        for (int y = y0; y < y0 + CHUNK; ++y) {
            const float4 o3 = step(y);
            if (st_ok)
                *reinterpret_cast<float4*>(sp) = o3;
            sp += W;
        }
    }
}

__global__ __launch_bounds__(128, 4)       // cap 128 regs -> 4 blocks/SM
void pm_fused3(const float* __restrict__ in, float* __restrict__ out)
{
    const int lane = threadIdx.x & 31;
    const int warp = threadIdx.x >> 5;

    // flattened work item: 10 strips x 14 bands x 16 images = 2240 warps
    const int item  = blockIdx.x * 4 + warp;
    const int image = item / (NSTRIP * NBANDS);
    const int rem   = item - image * (NSTRIP * NBANDS);
    const int strip = rem / NBANDS;
    const int band  = rem - strip * NBANDS;

    const int x0 = strip * OUTWC - HALO + lane * 4;
    const int y0 = band * CHUNK;
    const int nrows = (band == NBANDS - 1) ? (H - y0) : CHUNK;   // 62 or 74

    const size_t plane = (size_t)image * (size_t)(H * W);
    const float* __restrict__ img = in  + plane;
    float*       __restrict__ op  = out + plane;

    const bool colv  = (x0 >= 0) && (x0 + 4 <= W);
    const bool st_ok = colv && (lane >= HALO / 4) && (lane < 32 - HALO / 4);

    const bool interior = (strip >= 1) && (strip <= NSTRIP - 2) &&
                          (band >= 1) && (y0 + CHUNK + 6 < H);

    if (interior)
        run_strip<false>(img, op, x0, y0, CHUNK, true, st_ok);
    else
        run_strip<true>(img, op, x0, y0, nrows, colv, st_ok);
}

extern "C" void kernel_launch(void* const* d_in, const int* in_sizes, int n_in,
                              void* d_out, int out_size)
{
    const float* image = (const float*)d_in[0];
    float* out = (float*)d_out;

    // 2240 work items / 4 warps per block = 560 blocks: exactly one wave
    // at 4 blocks/SM residency (592 slots on 148 SMs).
    pm_fused3<<<560, 128>>>(image, out);
}